// round 1
// baseline (speedup 1.0000x reference)
#include <cuda_runtime.h>
#include <cuda_bf16.h>
#include <math.h>
#include <float.h>

// ---------------- problem constants ----------------
#define NN      20000      // nodes
#define TT      8          // timesteps
#define DS      16         // static feat
#define DD      8          // dynamic feat
#define EE      320000     // edges (raw)
#define ETOT    (EE + NN)  // + self loops
#define HL      128        // lstm hidden
#define GH      4          // heads
#define GC      128        // channels/head
#define HC      512        // GH*GC
#define EMB     64
#define IN1     144        // DS + HL
#define KLSTM   136        // DD + HL

// ---------------- scratch (device globals; no allocs allowed) ----------------
__device__ __align__(16) float g_h[NN * HL];
__device__ __align__(16) float g_c[NN * HL];
__device__ __align__(16) float g_cat[NN * IN1];     // concat buffer (lstm: 136 wide / gnn: 144 wide)
__device__ __align__(16) float g_feat[NN * HC];     // lstm gates, then GAT output / BN in-place
__device__ __align__(16) float g_xl[NN * HC];
__device__ __align__(16) float g_xr[NN * HC];
__device__ __align__(16) float g_s[(size_t)ETOT * GH];  // edge scores -> alpha (in place)
__device__ __align__(16) float g_bnsum[2 * HC];         // [sum | sumsq]
__device__ __align__(16) float g_bnsc[2 * HC];          // [scale | shift]
__device__ __align__(16) float g_wcat[HC * KLSTM];      // [W_ih | W_hh]
__device__ __align__(16) float g_bcat[HC];
__device__ __align__(16) int   g_counts[NN];
__device__ __align__(16) int   g_rowoff[NN + 1];
__device__ __align__(16) int   g_cursor[NN];
__device__ __align__(16) int   g_eid[ETOT];
__device__ __align__(16) int   g_src[ETOT];
__device__ __align__(16) int   g_dst[ETOT];

// ---------------- generic SGEMM: C[m,n] = sum_k A[m,k]*B[n,k] (+bias[n]) ----------------
// requirements: N % 64 == 0, K % 8 == 0, lda/ldb even, pointers 8B aligned. M guarded.
#define TM 64
#define TN 64
#define TK 8

__global__ void sgemm_nt(const float* __restrict__ A, const float* __restrict__ B,
                         float* __restrict__ C, const float* __restrict__ bias,
                         int M, int Nc, int K, int lda, int ldb, int ldc)
{
    __shared__ float As[TK][TM];
    __shared__ float Bs[TK][TN];
    int tid = threadIdx.x;                 // 256
    int bm = blockIdx.y * TM;
    int bn = blockIdx.x * TN;
    int tx = tid & 15, ty = tid >> 4;

    int la_m = tid >> 2;          // 0..63
    int la_k = (tid & 3) * 2;     // 0,2,4,6

    float acc[4][4];
#pragma unroll
    for (int i = 0; i < 4; i++)
#pragma unroll
        for (int j = 0; j < 4; j++) acc[i][j] = 0.f;

    for (int k0 = 0; k0 < K; k0 += TK) {
        int gm = bm + la_m;
        float2 av = make_float2(0.f, 0.f);
        if (gm < M) av = *(const float2*)&A[(size_t)gm * lda + k0 + la_k];
        As[la_k][la_m]     = av.x;
        As[la_k + 1][la_m] = av.y;

        int gn = bn + la_m;
        float2 bv = *(const float2*)&B[(size_t)gn * ldb + k0 + la_k];
        Bs[la_k][la_m]     = bv.x;
        Bs[la_k + 1][la_m] = bv.y;
        __syncthreads();

#pragma unroll
        for (int k = 0; k < TK; ++k) {
            float a[4], b[4];
            *(float4*)a = *(const float4*)&As[k][4 * ty];
            *(float4*)b = *(const float4*)&Bs[k][4 * tx];
#pragma unroll
            for (int i = 0; i < 4; i++)
#pragma unroll
                for (int j = 0; j < 4; j++) acc[i][j] += a[i] * b[j];
        }
        __syncthreads();
    }

#pragma unroll
    for (int i = 0; i < 4; i++) {
        int m = bm + 4 * ty + i;
        if (m >= M) continue;
#pragma unroll
        for (int j = 0; j < 4; j++) {
            int n = bn + 4 * tx + j;
            float v = acc[i][j];
            if (bias) v += bias[n];
            C[(size_t)m * ldc + n] = v;
        }
    }
}

// ---------------- setup kernels ----------------
__global__ void build_wcat(const float* __restrict__ Wih, const float* __restrict__ Whh,
                           const float* __restrict__ bih, const float* __restrict__ bhh)
{
    int i = blockIdx.x * blockDim.x + threadIdx.x;
    if (i < HC * KLSTM) {
        int j = i / KLSTM, k = i % KLSTM;
        g_wcat[i] = (k < DD) ? Wih[j * DD + k] : Whh[j * HL + (k - DD)];
    }
    if (i < HC) g_bcat[i] = bih[i] + bhh[i];
}

__global__ void fill_edges(const int* __restrict__ ei)
{
    int e = blockIdx.x * blockDim.x + threadIdx.x;
    if (e >= ETOT) return;
    int s, d;
    if (e < EE) { s = ei[e]; d = ei[EE + e]; }
    else        { s = d = e - EE; }
    g_src[e] = s; g_dst[e] = d;
    atomicAdd(&g_counts[d], 1);
}

__global__ void scan_rowoff()
{
    __shared__ int part[1024];
    int tid = threadIdx.x;
    const int chunk = (NN + 1023) / 1024;
    int start = tid * chunk;
    int lim = min(start + chunk, NN);
    int s = 0;
    for (int i = start; i < lim; i++) s += g_counts[i];
    part[tid] = s;
    __syncthreads();
    for (int off = 1; off < 1024; off <<= 1) {
        int v = (tid >= off) ? part[tid - off] : 0;
        __syncthreads();
        part[tid] += v;
        __syncthreads();
    }
    int run = (tid == 0) ? 0 : part[tid - 1];
    for (int i = start; i < lim; i++) { g_rowoff[i] = run; run += g_counts[i]; }
    if (tid == 1023) g_rowoff[NN] = part[1023];
}

__global__ void scatter_edges()
{
    int e = blockIdx.x * blockDim.x + threadIdx.x;
    if (e >= ETOT) return;
    int pos = atomicAdd(&g_cursor[g_dst[e]], 1);
    g_eid[pos] = e;
}

// ---------------- LSTM ----------------
__global__ void lstm_concat(const float* __restrict__ dyn, int t)
{
    int i = blockIdx.x * blockDim.x + threadIdx.x;
    if (i >= NN * KLSTM) return;
    int n = i / KLSTM, k = i % KLSTM;
    g_cat[i] = (k < DD) ? dyn[(size_t)n * TT * DD + t * DD + k] : g_h[n * HL + (k - DD)];
}

__device__ __forceinline__ float sigm(float x) { return 1.f / (1.f + expf(-x)); }

__global__ void lstm_point()
{
    int i = blockIdx.x * blockDim.x + threadIdx.x;
    if (i >= NN * HL) return;
    int n = i / HL, j = i % HL;
    const float* G = &g_feat[(size_t)n * HC];
    float ig = sigm(G[j]);
    float fg = sigm(G[HL + j]);
    float gg = tanhf(G[2 * HL + j]);
    float og = sigm(G[3 * HL + j]);
    float c = fg * g_c[i] + ig * gg;
    g_c[i] = c;
    g_h[i] = og * tanhf(c);
}

__global__ void gnn_concat(const float* __restrict__ xs)
{
    int i = blockIdx.x * blockDim.x + threadIdx.x;
    if (i >= NN * IN1) return;
    int n = i / IN1, k = i % IN1;
    g_cat[i] = (k < DS) ? xs[n * DS + k] : g_h[n * HL + (k - DS)];
}

// ---------------- GAT ----------------
__global__ void gat_scores(const float* __restrict__ att)
{
    int warp = (blockIdx.x * blockDim.x + threadIdx.x) >> 5;
    int lane = threadIdx.x & 31;
    if (warp >= ETOT) return;
    const float* xls = &g_xl[(size_t)g_src[warp] * HC];
    const float* xrd = &g_xr[(size_t)g_dst[warp] * HC];
#pragma unroll
    for (int h = 0; h < GH; ++h) {
        float p = 0.f;
#pragma unroll
        for (int c = lane; c < GC; c += 32) {
            float v = xls[h * GC + c] + xrd[h * GC + c];
            v = v > 0.f ? v : 0.2f * v;
            p += v * __ldg(&att[h * GC + c]);
        }
#pragma unroll
        for (int o = 16; o; o >>= 1) p += __shfl_xor_sync(0xffffffffu, p, o);
        if (lane == 0) g_s[(size_t)warp * GH + h] = p;
    }
}

__global__ void gat_softmax()
{
    int d = (blockIdx.x * blockDim.x + threadIdx.x) >> 5;
    int lane = threadIdx.x & 31;
    if (d >= NN) return;
    int beg = g_rowoff[d], end = g_rowoff[d + 1];
    float m[GH], den[GH];
#pragma unroll
    for (int h = 0; h < GH; h++) { m[h] = -FLT_MAX; den[h] = 0.f; }
    for (int j = beg + lane; j < end; j += 32) {
        int e = g_eid[j];
#pragma unroll
        for (int h = 0; h < GH; h++) m[h] = fmaxf(m[h], g_s[(size_t)e * GH + h]);
    }
#pragma unroll
    for (int h = 0; h < GH; h++)
#pragma unroll
        for (int o = 16; o; o >>= 1) m[h] = fmaxf(m[h], __shfl_xor_sync(0xffffffffu, m[h], o));
    for (int j = beg + lane; j < end; j += 32) {
        int e = g_eid[j];
#pragma unroll
        for (int h = 0; h < GH; h++) den[h] += expf(g_s[(size_t)e * GH + h] - m[h]);
    }
#pragma unroll
    for (int h = 0; h < GH; h++)
#pragma unroll
        for (int o = 16; o; o >>= 1) den[h] += __shfl_xor_sync(0xffffffffu, den[h], o);
    for (int j = beg + lane; j < end; j += 32) {
        int e = g_eid[j];
#pragma unroll
        for (int h = 0; h < GH; h++)
            g_s[(size_t)e * GH + h] = expf(g_s[(size_t)e * GH + h] - m[h]) / den[h];
    }
}

__global__ void gat_agg()
{
    int d = blockIdx.x;
    int f = threadIdx.x;          // 0..511
    int h = f >> 7;
    int beg = g_rowoff[d], end = g_rowoff[d + 1];
    float acc = 0.f;
    for (int j = beg; j < end; ++j) {
        int e = g_eid[j];
        acc += g_s[(size_t)e * GH + h] * g_xl[(size_t)g_src[e] * HC + f];
    }
    g_feat[(size_t)d * HC + f] = acc;
}

// ---------------- BatchNorm ----------------
__global__ void bn_reduce()
{
    int c = threadIdx.x;          // 512
    float s = 0.f, ss = 0.f;
    for (int r = blockIdx.x; r < NN; r += gridDim.x) {
        float v = g_feat[(size_t)r * HC + c];
        s += v; ss += v * v;
    }
    atomicAdd(&g_bnsum[c], s);
    atomicAdd(&g_bnsum[HC + c], ss);
}

__global__ void bn_final(const float* __restrict__ gamma, const float* __restrict__ beta)
{
    int c = threadIdx.x;
    float mean = g_bnsum[c] / (float)NN;
    float var  = g_bnsum[HC + c] / (float)NN - mean * mean;
    float k = gamma[c] * rsqrtf(var + 1e-5f);
    g_bnsc[c] = k;
    g_bnsc[HC + c] = beta[c] - mean * k;
}

__global__ void bn_norm_relu()
{
    int i = blockIdx.x * blockDim.x + threadIdx.x;
    if (i >= NN * HC) return;
    int c = i & (HC - 1);
    float v = g_feat[i] * g_bnsc[c] + g_bnsc[HC + c];
    g_feat[i] = v > 0.f ? v : 0.f;
}

// ---------------- host ----------------
static void* sym(const void* s) { void* p = nullptr; cudaGetSymbolAddress(&p, s); return p; }

extern "C" void kernel_launch(void* const* d_in, const int* in_sizes, int n_in,
                              void* d_out, int out_size)
{
    const float* x_static = (const float*)d_in[0];
    const float* dyn      = (const float*)d_in[1];
    const int*   ei       = (const int*)  d_in[2];
    const float* Wih      = (const float*)d_in[3];
    const float* Whh      = (const float*)d_in[4];
    const float* bih      = (const float*)d_in[5];
    const float* bhh      = (const float*)d_in[6];
    const float* Wl1      = (const float*)d_in[7];
    const float* Wr1      = (const float*)d_in[8];
    const float* att1     = (const float*)d_in[9];
    const float* Wl2      = (const float*)d_in[11];
    const float* Wr2      = (const float*)d_in[12];
    const float* att2     = (const float*)d_in[13];
    const float* gamma1   = (const float*)d_in[15];
    const float* beta1    = (const float*)d_in[16];
    const float* gamma2   = (const float*)d_in[17];
    const float* beta2    = (const float*)d_in[18];
    const float* Wp       = (const float*)d_in[19];
    const float* bp       = (const float*)d_in[20];
    float* out = (float*)d_out;

    float* pcat  = (float*)sym(g_cat);
    float* pfeat = (float*)sym(g_feat);
    float* pxl   = (float*)sym(g_xl);
    float* pxr   = (float*)sym(g_xr);
    float* pwcat = (float*)sym(g_wcat);
    float* pbcat = (float*)sym(g_bcat);
    float* ph    = (float*)sym(g_h);
    float* pc    = (float*)sym(g_c);
    float* psum  = (float*)sym(g_bnsum);
    int*   pcnt  = (int*)  sym(g_counts);
    int*   prow  = (int*)  sym(g_rowoff);
    int*   pcur  = (int*)  sym(g_cursor);

    // ---- setup: weights, CSR, state ----
    build_wcat<<<(HC * KLSTM + 255) / 256, 256>>>(Wih, Whh, bih, bhh);
    cudaMemsetAsync(pcnt, 0, NN * sizeof(int));
    fill_edges<<<(ETOT + 255) / 256, 256>>>(ei);
    scan_rowoff<<<1, 1024>>>();
    cudaMemcpyAsync(pcur, prow, NN * sizeof(int), cudaMemcpyDeviceToDevice);
    scatter_edges<<<(ETOT + 255) / 256, 256>>>();
    cudaMemsetAsync(ph, 0, NN * HL * sizeof(float));
    cudaMemsetAsync(pc, 0, NN * HL * sizeof(float));

    dim3 gemm_blk(256);
    const int MB = (NN + TM - 1) / TM;  // 313

    for (int t = 0; t < TT; ++t) {
        // ---- LSTM step ----
        lstm_concat<<<(NN * KLSTM + 255) / 256, 256>>>(dyn, t);
        sgemm_nt<<<dim3(HC / TN, MB), gemm_blk>>>(pcat, pwcat, pfeat, pbcat,
                                                  NN, HC, KLSTM, KLSTM, KLSTM, HC);
        lstm_point<<<(NN * HL + 255) / 256, 256>>>();

        // ---- GAT layer 1 ----
        gnn_concat<<<(NN * IN1 + 255) / 256, 256>>>(x_static);
        sgemm_nt<<<dim3(HC / TN, MB), gemm_blk>>>(pcat, Wl1, pxl, nullptr,
                                                  NN, HC, IN1, IN1, IN1, HC);
        sgemm_nt<<<dim3(HC / TN, MB), gemm_blk>>>(pcat, Wr1, pxr, nullptr,
                                                  NN, HC, IN1, IN1, IN1, HC);
        gat_scores<<<(ETOT * 32 + 127) / 128, 128>>>(att1);
        gat_softmax<<<(NN * 32 + 127) / 128, 128>>>();
        gat_agg<<<NN, HC>>>();
        cudaMemsetAsync(psum, 0, 2 * HC * sizeof(float));
        bn_reduce<<<256, HC>>>();
        bn_final<<<1, HC>>>(gamma1, beta1);
        bn_norm_relu<<<(NN * HC + 255) / 256, 256>>>();

        // ---- GAT layer 2 ----
        sgemm_nt<<<dim3(HC / TN, MB), gemm_blk>>>(pfeat, Wl2, pxl, nullptr,
                                                  NN, HC, HC, HC, HC, HC);
        sgemm_nt<<<dim3(HC / TN, MB), gemm_blk>>>(pfeat, Wr2, pxr, nullptr,
                                                  NN, HC, HC, HC, HC, HC);
        gat_scores<<<(ETOT * 32 + 127) / 128, 128>>>(att2);
        gat_softmax<<<(NN * 32 + 127) / 128, 128>>>();
        gat_agg<<<NN, HC>>>();
        cudaMemsetAsync(psum, 0, 2 * HC * sizeof(float));
        bn_reduce<<<256, HC>>>();
        bn_final<<<1, HC>>>(gamma2, beta2);
        bn_norm_relu<<<(NN * HC + 255) / 256, 256>>>();

        // ---- output projection: out[:, t, :] ----
        sgemm_nt<<<dim3(EMB / TN, MB), gemm_blk>>>(pfeat, Wp, out + t * EMB, bp,
                                                   NN, EMB, HC, HC, HC, TT * EMB);
    }
    (void)in_sizes; (void)n_in; (void)out_size;
}

// round 4
// speedup vs baseline: 1.8769x; 1.8769x over previous
#include <cuda_runtime.h>
#include <cuda_bf16.h>
#include <math.h>
#include <float.h>

// ---------------- problem constants ----------------
#define NN      20000      // nodes
#define TT      8          // timesteps
#define DS      16         // static feat
#define DD      8          // dynamic feat
#define EE      320000     // edges (raw)
#define ETOT    (EE + NN)  // + self loops
#define HL      128        // lstm hidden
#define GH      4          // heads
#define GC      128        // channels/head
#define HC      512        // GH*GC
#define HC2     1024       // combined xl|xr width
#define EMB     64
#define IN1     144        // DS + HL
#define KLSTM   136        // DD + HL

// ---------------- scratch (device globals; no allocs allowed) ----------------
__device__ __align__(16) float g_h[NN * HL];
__device__ __align__(16) float g_c[NN * HL];
__device__ __align__(16) float g_cat[NN * IN1];         // concat input buffer
__device__ __align__(16) float g_feat[NN * HC];         // lstm gates / GAT out / BN in-place
__device__ __align__(16) float g_xlr[(size_t)NN * HC2]; // [xl | xr]
__device__ __align__(16) float g_s[(size_t)ETOT * GH];  // edge scores -> alpha (in place)
__device__ __align__(16) float g_bnsum[2 * HC];         // [sum | sumsq]
__device__ __align__(16) float g_bnsc[2 * HC];          // [scale | shift]
__device__ __align__(16) float g_wcat[HC * KLSTM];      // [W_ih | W_hh]
__device__ __align__(16) float g_bcat[HC];
__device__ __align__(16) float g_w1[HC2 * IN1];         // [Wl1 ; Wr1]
__device__ __align__(16) float g_w2[HC2 * HC];          // [Wl2 ; Wr2]
__device__ __align__(16) int   g_counts[NN];
__device__ __align__(16) int   g_rowoff[NN + 1];
__device__ __align__(16) int   g_cursor[NN];
__device__ __align__(16) int   g_eid[ETOT];
__device__ __align__(16) int   g_src[ETOT];
__device__ __align__(16) int   g_dst[ETOT];

// =====================================================================
// Fast SGEMM: C[m,n] = sum_k A[m,k]*B[n,k] (+bias[n])
// 128x128 tile, TK=8, double-buffered smem, 8x8 per thread (4+4 split).
// Requires: Nc % 128 == 0, K % 8 == 0, lda/ldb % 4 == 0. M guarded.
// =====================================================================
__global__ __launch_bounds__(256, 2) void sgemm128(
    const float* __restrict__ A, const float* __restrict__ B,
    float* __restrict__ C, const float* __restrict__ bias,
    int M, int K, int lda, int ldb, int ldc)
{
    __shared__ float As[2][8][128];
    __shared__ float Bs[2][8][128];

    const int tid = threadIdx.x;
    const int bm = blockIdx.y * 128;
    const int bn = blockIdx.x * 128;
    const int tx = tid & 15;        // 0..15
    const int ty = tid >> 4;        // 0..15

    const int lr = tid >> 1;        // 0..127 row within tile
    const int lk = (tid & 1) * 4;   // 0 or 4

    const int gm = bm + lr;
    const bool mok = gm < M;
    const float* Ap = A + (size_t)(mok ? gm : 0) * lda + lk;
    const float* Bp = B + (size_t)(bn + lr) * ldb + lk;

    float acc[8][8];
#pragma unroll
    for (int i = 0; i < 8; i++)
#pragma unroll
        for (int j = 0; j < 8; j++) acc[i][j] = 0.f;

    const int nk = K >> 3;
    float4 a = mok ? *(const float4*)Ap : make_float4(0.f, 0.f, 0.f, 0.f);
    float4 b = *(const float4*)Bp;

    int buf = 0;
    for (int kt = 0; kt < nk; ++kt) {
        As[buf][lk + 0][lr] = a.x;
        As[buf][lk + 1][lr] = a.y;
        As[buf][lk + 2][lr] = a.z;
        As[buf][lk + 3][lr] = a.w;
        Bs[buf][lk + 0][lr] = b.x;
        Bs[buf][lk + 1][lr] = b.y;
        Bs[buf][lk + 2][lr] = b.z;
        Bs[buf][lk + 3][lr] = b.w;
        __syncthreads();

        if (kt + 1 < nk) {
            int off = (kt + 1) * 8;
            if (mok) a = *(const float4*)(Ap + off);
            b = *(const float4*)(Bp + off);
        }

#pragma unroll
        for (int k = 0; k < 8; ++k) {
            float ar[8], br[8];
            *(float4*)(ar)     = *(const float4*)&As[buf][k][ty * 4];
            *(float4*)(ar + 4) = *(const float4*)&As[buf][k][64 + ty * 4];
            *(float4*)(br)     = *(const float4*)&Bs[buf][k][tx * 4];
            *(float4*)(br + 4) = *(const float4*)&Bs[buf][k][64 + tx * 4];
#pragma unroll
            for (int i = 0; i < 8; i++)
#pragma unroll
                for (int j = 0; j < 8; j++) acc[i][j] += ar[i] * br[j];
        }
        buf ^= 1;
    }

#pragma unroll
    for (int i = 0; i < 8; i++) {
        int m = (i < 4) ? (bm + ty * 4 + i) : (bm + 64 + ty * 4 + i - 4);
        if (m >= M) continue;
        float* Cp = C + (size_t)m * ldc + bn;
        float4 v0 = make_float4(acc[i][0], acc[i][1], acc[i][2], acc[i][3]);
        float4 v1 = make_float4(acc[i][4], acc[i][5], acc[i][6], acc[i][7]);
        if (bias) {
            const float* b0 = bias + bn + tx * 4;
            const float* b1 = bias + bn + 64 + tx * 4;
            v0.x += b0[0]; v0.y += b0[1]; v0.z += b0[2]; v0.w += b0[3];
            v1.x += b1[0]; v1.y += b1[1]; v1.z += b1[2]; v1.w += b1[3];
        }
        *(float4*)(Cp + tx * 4)      = v0;
        *(float4*)(Cp + 64 + tx * 4) = v1;
    }
}

// ---------------- small SGEMM (64x64) for the EMB=64 projection ----------------
#define TM 64
#define TN 64
#define TK 8
__global__ void sgemm_nt(const float* __restrict__ A, const float* __restrict__ B,
                         float* __restrict__ C, const float* __restrict__ bias,
                         int M, int Nc, int K, int lda, int ldb, int ldc)
{
    __shared__ float As[TK][TM];
    __shared__ float Bs[TK][TN];
    int tid = threadIdx.x;
    int bm = blockIdx.y * TM;
    int bn = blockIdx.x * TN;
    int tx = tid & 15, ty = tid >> 4;
    int la_m = tid >> 2;
    int la_k = (tid & 3) * 2;

    float acc[4][4];
#pragma unroll
    for (int i = 0; i < 4; i++)
#pragma unroll
        for (int j = 0; j < 4; j++) acc[i][j] = 0.f;

    for (int k0 = 0; k0 < K; k0 += TK) {
        int gm = bm + la_m;
        float2 av = make_float2(0.f, 0.f);
        if (gm < M) av = *(const float2*)&A[(size_t)gm * lda + k0 + la_k];
        As[la_k][la_m] = av.x;
        As[la_k + 1][la_m] = av.y;
        int gn = bn + la_m;
        float2 bv = *(const float2*)&B[(size_t)gn * ldb + k0 + la_k];
        Bs[la_k][la_m] = bv.x;
        Bs[la_k + 1][la_m] = bv.y;
        __syncthreads();
#pragma unroll
        for (int k = 0; k < TK; ++k) {
            float a[4], b[4];
            *(float4*)a = *(const float4*)&As[k][4 * ty];
            *(float4*)b = *(const float4*)&Bs[k][4 * tx];
#pragma unroll
            for (int i = 0; i < 4; i++)
#pragma unroll
                for (int j = 0; j < 4; j++) acc[i][j] += a[i] * b[j];
        }
        __syncthreads();
    }
#pragma unroll
    for (int i = 0; i < 4; i++) {
        int m = bm + 4 * ty + i;
        if (m >= M) continue;
#pragma unroll
        for (int j = 0; j < 4; j++) {
            int n = bn + 4 * tx + j;
            float v = acc[i][j];
            if (bias) v += bias[n];
            C[(size_t)m * ldc + n] = v;
        }
    }
}

// ---------------- setup kernels ----------------
__global__ void build_wcat(const float* __restrict__ Wih, const float* __restrict__ Whh,
                           const float* __restrict__ bih, const float* __restrict__ bhh)
{
    int i = blockIdx.x * blockDim.x + threadIdx.x;
    if (i < HC * KLSTM) {
        int j = i / KLSTM, k = i % KLSTM;
        g_wcat[i] = (k < DD) ? Wih[j * DD + k] : Whh[j * HL + (k - DD)];
    }
    if (i < HC) g_bcat[i] = bih[i] + bhh[i];
}

__global__ void build_w1(const float* __restrict__ Wl, const float* __restrict__ Wr)
{
    int i = blockIdx.x * blockDim.x + threadIdx.x;
    if (i >= HC2 * IN1) return;
    int r = i / IN1, k = i % IN1;
    g_w1[i] = (r < HC) ? Wl[r * IN1 + k] : Wr[(r - HC) * IN1 + k];
}

__global__ void build_w2(const float* __restrict__ Wl, const float* __restrict__ Wr)
{
    int i = blockIdx.x * blockDim.x + threadIdx.x;
    if (i >= HC2 * HC) return;
    int r = i / HC, k = i % HC;
    g_w2[i] = (r < HC) ? Wl[r * HC + k] : Wr[(r - HC) * HC + k];
}

__global__ void fill_edges(const int* __restrict__ ei)
{
    int e = blockIdx.x * blockDim.x + threadIdx.x;
    if (e >= ETOT) return;
    int s, d;
    if (e < EE) { s = ei[e]; d = ei[EE + e]; }
    else        { s = d = e - EE; }
    g_src[e] = s; g_dst[e] = d;
    atomicAdd(&g_counts[d], 1);
}

__global__ void scan_rowoff()
{
    __shared__ int part[1024];
    int tid = threadIdx.x;
    const int chunk = (NN + 1023) / 1024;
    int start = tid * chunk;
    int lim = min(start + chunk, NN);
    int s = 0;
    for (int i = start; i < lim; i++) s += g_counts[i];
    part[tid] = s;
    __syncthreads();
    for (int off = 1; off < 1024; off <<= 1) {
        int v = (tid >= off) ? part[tid - off] : 0;
        __syncthreads();
        part[tid] += v;
        __syncthreads();
    }
    int run = (tid == 0) ? 0 : part[tid - 1];
    for (int i = start; i < lim; i++) { g_rowoff[i] = run; run += g_counts[i]; }
    if (tid == 1023) g_rowoff[NN] = part[1023];
}

__global__ void scatter_edges()
{
    int e = blockIdx.x * blockDim.x + threadIdx.x;
    if (e >= ETOT) return;
    int pos = atomicAdd(&g_cursor[g_dst[e]], 1);
    g_eid[pos] = e;
}

// ---------------- LSTM ----------------
__global__ void lstm_concat(const float* __restrict__ dyn, int t)
{
    int i = blockIdx.x * blockDim.x + threadIdx.x;
    if (i >= NN * KLSTM) return;
    int n = i / KLSTM, k = i % KLSTM;
    g_cat[i] = (k < DD) ? dyn[(size_t)n * TT * DD + t * DD + k] : g_h[n * HL + (k - DD)];
}

__device__ __forceinline__ float sigm(float x) { return 1.f / (1.f + expf(-x)); }

__global__ void lstm_point()
{
    int i = blockIdx.x * blockDim.x + threadIdx.x;
    if (i >= NN * HL) return;
    int n = i / HL, j = i % HL;
    const float* G = &g_feat[(size_t)n * HC];
    float ig = sigm(G[j]);
    float fg = sigm(G[HL + j]);
    float gg = tanhf(G[2 * HL + j]);
    float og = sigm(G[3 * HL + j]);
    float c = fg * g_c[i] + ig * gg;
    g_c[i] = c;
    g_h[i] = og * tanhf(c);
}

__global__ void gnn_concat(const float* __restrict__ xs)
{
    int i = blockIdx.x * blockDim.x + threadIdx.x;
    if (i >= NN * IN1) return;
    int n = i / IN1, k = i % IN1;
    g_cat[i] = (k < DS) ? xs[n * DS + k] : g_h[n * HL + (k - DS)];
}

// ---------------- GAT: fused scores + online softmax (one warp per dst) ----------------
__global__ void gat_attn(const float* __restrict__ att)
{
    int d = (blockIdx.x * blockDim.x + threadIdx.x) >> 5;
    int lane = threadIdx.x & 31;
    if (d >= NN) return;
    int beg = g_rowoff[d], end = g_rowoff[d + 1];

    // xr[dst] and att into registers (channel idx = q*32 + lane)
    float xr[16], at[16];
    const float* xrp = g_xlr + (size_t)d * HC2 + HC;
#pragma unroll
    for (int q = 0; q < 16; q++) {
        xr[q] = xrp[q * 32 + lane];
        at[q] = __ldg(&att[q * 32 + lane]);
    }

    float m0 = -FLT_MAX, m1 = -FLT_MAX, m2 = -FLT_MAX, m3 = -FLT_MAX;
    float d0 = 0.f, d1 = 0.f, d2 = 0.f, d3 = 0.f;

    for (int j = beg; j < end; ++j) {
        int e = g_eid[j];
        const float* xlp = g_xlr + (size_t)g_src[e] * HC2;
        float p0 = 0.f, p1 = 0.f, p2 = 0.f, p3 = 0.f;
#pragma unroll
        for (int q = 0; q < 16; q++) {
            float v = xlp[q * 32 + lane] + xr[q];
            v = v > 0.f ? v : 0.2f * v;
            float pv = v * at[q];
            if (q < 4)       p0 += pv;
            else if (q < 8)  p1 += pv;
            else if (q < 12) p2 += pv;
            else             p3 += pv;
        }
#pragma unroll
        for (int o = 16; o; o >>= 1) {
            p0 += __shfl_xor_sync(0xffffffffu, p0, o);
            p1 += __shfl_xor_sync(0xffffffffu, p1, o);
            p2 += __shfl_xor_sync(0xffffffffu, p2, o);
            p3 += __shfl_xor_sync(0xffffffffu, p3, o);
        }
        // online softmax update (all lanes hold identical p values)
        float nm;
        nm = fmaxf(m0, p0); d0 = d0 * expf(m0 - nm) + expf(p0 - nm); m0 = nm;
        nm = fmaxf(m1, p1); d1 = d1 * expf(m1 - nm) + expf(p1 - nm); m1 = nm;
        nm = fmaxf(m2, p2); d2 = d2 * expf(m2 - nm) + expf(p2 - nm); m2 = nm;
        nm = fmaxf(m3, p3); d3 = d3 * expf(m3 - nm) + expf(p3 - nm); m3 = nm;
        if (lane == 0) {
            float* sp = &g_s[(size_t)e * GH];
            sp[0] = p0; sp[1] = p1; sp[2] = p2; sp[3] = p3;
        }
    }
    // normalize pass
    for (int j = beg + lane; j < end; j += 32) {
        int e = g_eid[j];
        float* sp = &g_s[(size_t)e * GH];
        sp[0] = expf(sp[0] - m0) / d0;
        sp[1] = expf(sp[1] - m1) / d1;
        sp[2] = expf(sp[2] - m2) / d2;
        sp[3] = expf(sp[3] - m3) / d3;
    }
}

// ---------------- GAT aggregate: one block (512 thr) per dst ----------------
__global__ void gat_agg()
{
    int d = blockIdx.x;
    int f = threadIdx.x;          // 0..511
    int h = f >> 7;
    int beg = g_rowoff[d], end = g_rowoff[d + 1];
    float acc = 0.f;
    for (int j = beg; j < end; ++j) {
        int e = g_eid[j];
        acc += g_s[(size_t)e * GH + h] * g_xlr[(size_t)g_src[e] * HC2 + f];
    }
    g_feat[(size_t)d * HC + f] = acc;
}

// ---------------- BatchNorm ----------------
__global__ void bn_reduce()
{
    int c = threadIdx.x;          // 512
    float s = 0.f, ss = 0.f;
    for (int r = blockIdx.x; r < NN; r += gridDim.x) {
        float v = g_feat[(size_t)r * HC + c];
        s += v; ss += v * v;
    }
    atomicAdd(&g_bnsum[c], s);
    atomicAdd(&g_bnsum[HC + c], ss);
}

__global__ void bn_final(const float* __restrict__ gamma, const float* __restrict__ beta)
{
    int c = threadIdx.x;
    float mean = g_bnsum[c] / (float)NN;
    float var  = g_bnsum[HC + c] / (float)NN - mean * mean;
    float k = gamma[c] * rsqrtf(var + 1e-5f);
    g_bnsc[c] = k;
    g_bnsc[HC + c] = beta[c] - mean * k;
}

__global__ void bn_norm_relu()
{
    int i = blockIdx.x * blockDim.x + threadIdx.x;
    if (i >= NN * HC) return;
    int c = i & (HC - 1);
    float v = g_feat[i] * g_bnsc[c] + g_bnsc[HC + c];
    g_feat[i] = v > 0.f ? v : 0.f;
}

// ---------------- host ----------------
static void* sym(const void* s) { void* p = nullptr; cudaGetSymbolAddress(&p, s); return p; }

extern "C" void kernel_launch(void* const* d_in, const int* in_sizes, int n_in,
                              void* d_out, int out_size)
{
    const float* x_static = (const float*)d_in[0];
    const float* dyn      = (const float*)d_in[1];
    const int*   ei       = (const int*)  d_in[2];
    const float* Wih      = (const float*)d_in[3];
    const float* Whh      = (const float*)d_in[4];
    const float* bih      = (const float*)d_in[5];
    const float* bhh      = (const float*)d_in[6];
    const float* Wl1      = (const float*)d_in[7];
    const float* Wr1      = (const float*)d_in[8];
    const float* att1     = (const float*)d_in[9];
    const float* Wl2      = (const float*)d_in[11];
    const float* Wr2      = (const float*)d_in[12];
    const float* att2     = (const float*)d_in[13];
    const float* gamma1   = (const float*)d_in[15];
    const float* beta1    = (const float*)d_in[16];
    const float* gamma2   = (const float*)d_in[17];
    const float* beta2    = (const float*)d_in[18];
    const float* Wp       = (const float*)d_in[19];
    const float* bp       = (const float*)d_in[20];
    float* out = (float*)d_out;

    float* pcat  = (float*)sym(g_cat);
    float* pfeat = (float*)sym(g_feat);
    float* pxlr  = (float*)sym(g_xlr);
    float* pwcat = (float*)sym(g_wcat);
    float* pbcat = (float*)sym(g_bcat);
    float* pw1   = (float*)sym(g_w1);
    float* pw2   = (float*)sym(g_w2);
    float* ph    = (float*)sym(g_h);
    float* pc    = (float*)sym(g_c);
    float* psum  = (float*)sym(g_bnsum);
    int*   pcnt  = (int*)  sym(g_counts);
    int*   prow  = (int*)  sym(g_rowoff);
    int*   pcur  = (int*)  sym(g_cursor);

    // ---- setup: weights, CSR, state ----
    build_wcat<<<(HC * KLSTM + 255) / 256, 256>>>(Wih, Whh, bih, bhh);
    build_w1<<<(HC2 * IN1 + 255) / 256, 256>>>(Wl1, Wr1);
    build_w2<<<(HC2 * HC + 255) / 256, 256>>>(Wl2, Wr2);
    cudaMemsetAsync(pcnt, 0, NN * sizeof(int));
    fill_edges<<<(ETOT + 255) / 256, 256>>>(ei);
    scan_rowoff<<<1, 1024>>>();
    cudaMemcpyAsync(pcur, prow, NN * sizeof(int), cudaMemcpyDeviceToDevice);
    scatter_edges<<<(ETOT + 255) / 256, 256>>>();
    cudaMemsetAsync(ph, 0, NN * HL * sizeof(float));
    cudaMemsetAsync(pc, 0, NN * HL * sizeof(float));

    const int MB = (NN + 127) / 128;   // 157 M-tiles for sgemm128

    for (int t = 0; t < TT; ++t) {
        // ---- LSTM step ----
        lstm_concat<<<(NN * KLSTM + 255) / 256, 256>>>(dyn, t);
        sgemm128<<<dim3(HC / 128, MB), 256>>>(pcat, pwcat, pfeat, pbcat,
                                              NN, KLSTM, KLSTM, KLSTM, HC);
        lstm_point<<<(NN * HL + 255) / 256, 256>>>();

        // ---- GAT layer 1 ----
        gnn_concat<<<(NN * IN1 + 255) / 256, 256>>>(x_static);
        sgemm128<<<dim3(HC2 / 128, MB), 256>>>(pcat, pw1, pxlr, nullptr,
                                               NN, IN1, IN1, IN1, HC2);
        gat_attn<<<(NN * 32 + 127) / 128, 128>>>(att1);
        gat_agg<<<NN, HC>>>();
        cudaMemsetAsync(psum, 0, 2 * HC * sizeof(float));
        bn_reduce<<<256, HC>>>();
        bn_final<<<1, HC>>>(gamma1, beta1);
        bn_norm_relu<<<(NN * HC + 255) / 256, 256>>>();

        // ---- GAT layer 2 ----
        sgemm128<<<dim3(HC2 / 128, MB), 256>>>(pfeat, pw2, pxlr, nullptr,
                                               NN, HC, HC, HC, HC2);
        gat_attn<<<(NN * 32 + 127) / 128, 128>>>(att2);
        gat_agg<<<NN, HC>>>();
        cudaMemsetAsync(psum, 0, 2 * HC * sizeof(float));
        bn_reduce<<<256, HC>>>();
        bn_final<<<1, HC>>>(gamma2, beta2);
        bn_norm_relu<<<(NN * HC + 255) / 256, 256>>>();

        // ---- output projection: out[:, t, :] ----
        sgemm_nt<<<dim3(EMB / 64, (NN + 63) / 64), 256>>>(pfeat, Wp, out + t * EMB, bp,
                                                          NN, EMB, HC, HC, HC, TT * EMB);
    }
    (void)in_sizes; (void)n_in; (void)out_size;
}

// round 15
// speedup vs baseline: 2.5541x; 1.3608x over previous
#include <cuda_runtime.h>
#include <cuda_bf16.h>
#include <math.h>
#include <float.h>
#include <stdint.h>

// ---------------- problem constants ----------------
#define NN      20000
#define TT      8
#define DS      16
#define DD      8
#define EE      320000
#define ETOT    (EE + NN)
#define HL      128
#define GH      4
#define GC      128
#define HC      512
#define HC2     1024
#define EMB     64
#define IN1     144        // DS + HL
#define KLSTM   136        // DD + HL

// split-K widths (activations [hi|hi|lo], weights [hi|lo|hi]; zero padded)
#define KP1     448        // 3*144 = 432 -> 448
#define KP2     1536       // 3*512

// ---------------- scratch (device globals) ----------------
__device__ __align__(16) float g_h[NN * HL];
__device__ __align__(16) float g_c[NN * HL];
__device__ __align__(16) float g_feat[NN * HC];
__device__ __align__(16) float g_xlr[(size_t)NN * HC2];
__device__ __align__(16) float g_s[(size_t)ETOT * GH];
__device__ __align__(16) float g_bnsum[2 * HC];
__device__ __align__(16) float g_bnsc[2 * HC];
__device__ __align__(16) float g_bcat[HC];
__device__ __align__(16) __nv_bfloat16 g_a2[(size_t)NN * KP2];
__device__ __align__(16) __nv_bfloat16 g_wl[HC * KP1];
__device__ __align__(16) __nv_bfloat16 g_w1b[HC2 * KP1];
__device__ __align__(16) __nv_bfloat16 g_w2b[(size_t)HC2 * KP2];
__device__ __align__(16) __nv_bfloat16 g_wpb[EMB * KP2];
__device__ __align__(16) int g_counts[NN];
__device__ __align__(16) int g_rowoff[NN + 1];
__device__ __align__(16) int g_cursor[NN];
__device__ __align__(16) int g_eid[ETOT];
__device__ __align__(16) int g_src[ETOT];
__device__ __align__(16) int g_dst[ETOT];

// ---------------- helpers ----------------
__device__ __forceinline__ uint32_t smem_u32(const void* p) {
    uint32_t a;
    asm("{ .reg .u64 t; cvta.to.shared.u64 t, %1; cvt.u32.u64 %0, t; }" : "=r"(a) : "l"(p));
    return a;
}

__device__ __forceinline__ void mma16816(float* d, const uint32_t* a, const uint32_t* b)
{
    asm volatile(
        "mma.sync.aligned.m16n8k16.row.col.f32.bf16.bf16.f32 "
        "{%0,%1,%2,%3}, {%4,%5,%6,%7}, {%8,%9}, {%0,%1,%2,%3};"
        : "+f"(d[0]), "+f"(d[1]), "+f"(d[2]), "+f"(d[3])
        : "r"(a[0]), "r"(a[1]), "r"(a[2]), "r"(a[3]), "r"(b[0]), "r"(b[1]));
}

// =====================================================================
// Warp-MMA bf16 GEMM: C[m,n] = sum_k A[m,k]*B[n,k] (+bias[n]), fp32 acc.
// BM=128, BN=NT, BK=64. 256 threads = 8 warps (4 M x 2 N).
// A: [M, lda] bf16 (M guarded), B: [Ntot, ldb] bf16 (N exact).
// K consumed in chunks of 64; nch = K/64. cp.async double buffer.
// =====================================================================
template <int NT>
__global__ __launch_bounds__(256, 2)
void wgemm(const __nv_bfloat16* __restrict__ A, const __nv_bfloat16* __restrict__ B,
           float* __restrict__ C, const float* __restrict__ bias,
           int M, int lda, int ldb, int ldc, int nch)
{
    constexpr int LDSE  = 72;                 // smem row stride (elems) = 144B
    constexpr int ASZ   = 128 * LDSE;
    constexpr int BSZ   = NT * LDSE;
    constexpr int STAGE = ASZ + BSZ;          // elems per buffer
    constexpr int NWT   = NT / 16;            // n-tiles (of 8) per warp

    extern __shared__ __nv_bfloat16 smw[];
    const uint32_t sbase = smem_u32(smw);

    const int tid  = threadIdx.x;
    const int lane = tid & 31, wid = tid >> 5;
    const int bm = blockIdx.y * 128;
    const int bn = blockIdx.x * NT;
    const int wm = (wid >> 1) * 32;
    const int wn = (wid & 1) * (NT / 2);

    float acc[2][NWT][4];
#pragma unroll
    for (int mt = 0; mt < 2; mt++)
#pragma unroll
        for (int nt = 0; nt < NWT; nt++)
#pragma unroll
            for (int q = 0; q < 4; q++) acc[mt][nt][q] = 0.f;

    // per-thread load coordinates (16B vectors)
    const int lrow = tid >> 3;             // 0..31 (+32*i)
    const int lcol = (tid & 7) * 8;

    // ---- issue chunk c into buffer buf ----
    auto issue = [&](int c, int buf) {
        const int kof = c * 64;
        const uint32_t abase = sbase + (uint32_t)buf * STAGE * 2;
        const uint32_t bbase = abase + ASZ * 2;
#pragma unroll
        for (int i = 0; i < 4; i++) {
            int row = lrow + i * 32;
            uint32_t sa = abase + (uint32_t)(row * LDSE + lcol) * 2;
            int gr = bm + row;
            int sz = (gr < M) ? 16 : 0;
            if (gr >= M) gr = M - 1;       // keep address in-bounds; zfill anyway
            const void* g = A + (size_t)gr * lda + kof + lcol;
            asm volatile("cp.async.cg.shared.global [%0], [%1], 16, %2;"
                         :: "r"(sa), "l"(g), "r"(sz));
        }
#pragma unroll
        for (int i = 0; i < NT / 32; i++) {
            int row = lrow + i * 32;
            uint32_t sa = bbase + (uint32_t)(row * LDSE + lcol) * 2;
            const void* g = B + (size_t)(bn + row) * ldb + kof + lcol;
            asm volatile("cp.async.cg.shared.global [%0], [%1], 16;"
                         :: "r"(sa), "l"(g));
        }
        asm volatile("cp.async.commit_group;" ::: "memory");
    };

    // prologue
    issue(0, 0);
    asm volatile("cp.async.wait_group 0;" ::: "memory");
    __syncthreads();

    for (int c = 0; c < nch; ++c) {
        const int buf = c & 1;
        const uint32_t abase = sbase + (uint32_t)buf * STAGE * 2;
        const uint32_t bbase = abase + ASZ * 2;

        if (c + 1 < nch) issue(c + 1, 1 - buf);

#pragma unroll
        for (int ks = 0; ks < 4; ++ks) {
            uint32_t afr[2][4];
#pragma unroll
            for (int mt = 0; mt < 2; mt++) {
                uint32_t ad = abase +
                    (uint32_t)((wm + mt * 16 + (lane & 15)) * LDSE + ks * 16 + (lane >> 4) * 8) * 2;
                asm volatile("ldmatrix.sync.aligned.m8n8.x4.shared.b16 {%0,%1,%2,%3}, [%4];"
                             : "=r"(afr[mt][0]), "=r"(afr[mt][1]),
                               "=r"(afr[mt][2]), "=r"(afr[mt][3]) : "r"(ad));
            }
            uint32_t bfr[NWT][2];
#pragma unroll
            for (int p = 0; p < NWT / 2; p++) {
                int grp = lane >> 3, r = lane & 7;
                int nrow = wn + p * 16 + (grp >> 1) * 8 + r;
                int kcol = ks * 16 + (grp & 1) * 8;
                uint32_t bd = bbase + (uint32_t)(nrow * LDSE + kcol) * 2;
                asm volatile("ldmatrix.sync.aligned.m8n8.x4.shared.b16 {%0,%1,%2,%3}, [%4];"
                             : "=r"(bfr[2 * p][0]), "=r"(bfr[2 * p][1]),
                               "=r"(bfr[2 * p + 1][0]), "=r"(bfr[2 * p + 1][1]) : "r"(bd));
            }
#pragma unroll
            for (int mt = 0; mt < 2; mt++)
#pragma unroll
                for (int nt = 0; nt < NWT; nt++)
                    mma16816(acc[mt][nt], afr[mt], bfr[nt]);
        }

        if (c + 1 < nch) {
            asm volatile("cp.async.wait_group 0;" ::: "memory");
            __syncthreads();
        }
    }

    // epilogue
#pragma unroll
    for (int mt = 0; mt < 2; mt++) {
        int r0 = bm + wm + mt * 16 + (lane >> 2);
#pragma unroll
        for (int nt = 0; nt < NWT; nt++) {
            int n0 = bn + wn + nt * 8 + (lane & 3) * 2;
            float bx = 0.f, by = 0.f;
            if (bias) { bx = bias[n0]; by = bias[n0 + 1]; }
            if (r0 < M) {
                float2 v = make_float2(acc[mt][nt][0] + bx, acc[mt][nt][1] + by);
                *(float2*)(C + (size_t)r0 * ldc + n0) = v;
            }
            if (r0 + 8 < M) {
                float2 v = make_float2(acc[mt][nt][2] + bx, acc[mt][nt][3] + by);
                *(float2*)(C + (size_t)(r0 + 8) * ldc + n0) = v;
            }
        }
    }
}

// ---------------- bf16 split helpers ----------------
__device__ __forceinline__ __nv_bfloat16 bf_hi(float v) { return __float2bfloat16(v); }
__device__ __forceinline__ __nv_bfloat16 bf_lo(float v) {
    __nv_bfloat16 h = __float2bfloat16(v);
    return __float2bfloat16(v - __bfloat162float(h));
}

// ---------------- weight conversion: weights packed [hi | LO | hi] ----------------
// (activations are [hi | hi | lo]; staggered so K-segments give
//  Ahi*Whi + Ahi*Wlo + Alo*Whi ~= A*W)
__global__ void build_wlstm(const float* __restrict__ Wih, const float* __restrict__ Whh,
                            const float* __restrict__ bih, const float* __restrict__ bhh)
{
    int i = blockIdx.x * blockDim.x + threadIdx.x;
    if (i < HC) g_bcat[i] = bih[i] + bhh[i];
    if (i >= HC * KP1) return;
    int r = i / KP1, kk = i % KP1;
    int k = kk < 144 ? kk : kk < 288 ? kk - 144 : kk < 432 ? kk - 288 : -1;
    float v = 0.f;
    if (k >= 0 && k < KLSTM) v = (k < DD) ? Wih[r * DD + k] : Whh[r * HL + (k - DD)];
    g_wl[i] = (kk < 144) ? bf_hi(v) : (kk < 288) ? bf_lo(v) : bf_hi(v);
}

__global__ void build_w1b(const float* __restrict__ Wl, const float* __restrict__ Wr)
{
    int i = blockIdx.x * blockDim.x + threadIdx.x;
    if (i >= HC2 * KP1) return;
    int r = i / KP1, kk = i % KP1;
    int k = kk < 144 ? kk : kk < 288 ? kk - 144 : kk < 432 ? kk - 288 : -1;
    float v = 0.f;
    if (k >= 0) v = (r < HC) ? Wl[r * IN1 + k] : Wr[(r - HC) * IN1 + k];
    g_w1b[i] = (kk < 144) ? bf_hi(v) : (kk < 288) ? bf_lo(v) : bf_hi(v);
}

__global__ void build_w2b(const float* __restrict__ Wl, const float* __restrict__ Wr)
{
    size_t i = (size_t)blockIdx.x * blockDim.x + threadIdx.x;
    if (i >= (size_t)HC2 * KP2) return;
    int r = (int)(i / KP2), kk = (int)(i % KP2);
    int k = kk < 512 ? kk : kk < 1024 ? kk - 512 : kk - 1024;
    float v = (r < HC) ? Wl[r * HC + k] : Wr[(r - HC) * HC + k];
    g_w2b[i] = (kk < 512) ? bf_hi(v) : (kk < 1024) ? bf_lo(v) : bf_hi(v);
}

__global__ void build_wpb(const float* __restrict__ Wp)
{
    int i = blockIdx.x * blockDim.x + threadIdx.x;
    if (i >= EMB * KP2) return;
    int r = i / KP2, kk = i % KP2;
    int k = kk < 512 ? kk : kk < 1024 ? kk - 512 : kk - 1024;
    float v = Wp[r * HC + k];
    g_wpb[i] = (kk < 512) ? bf_hi(v) : (kk < 1024) ? bf_lo(v) : bf_hi(v);
}

// ---------------- CSR build ----------------
__global__ void fill_edges(const int* __restrict__ ei)
{
    int e = blockIdx.x * blockDim.x + threadIdx.x;
    if (e >= ETOT) return;
    int s, d;
    if (e < EE) { s = ei[e]; d = ei[EE + e]; }
    else        { s = d = e - EE; }
    g_src[e] = s; g_dst[e] = d;
    atomicAdd(&g_counts[d], 1);
}

__global__ void scan_rowoff()
{
    __shared__ int part[1024];
    int tid = threadIdx.x;
    const int chunk = (NN + 1023) / 1024;
    int start = tid * chunk;
    int lim = min(start + chunk, NN);
    int s = 0;
    for (int i = start; i < lim; i++) s += g_counts[i];
    part[tid] = s;
    __syncthreads();
    for (int off = 1; off < 1024; off <<= 1) {
        int v = (tid >= off) ? part[tid - off] : 0;
        __syncthreads();
        part[tid] += v;
        __syncthreads();
    }
    int run = (tid == 0) ? 0 : part[tid - 1];
    for (int i = start; i < lim; i++) { g_rowoff[i] = run; run += g_counts[i]; }
    if (tid == 1023) g_rowoff[NN] = part[1023];
}

__global__ void scatter_edges()
{
    int e = blockIdx.x * blockDim.x + threadIdx.x;
    if (e >= ETOT) return;
    int pos = atomicAdd(&g_cursor[g_dst[e]], 1);
    g_eid[pos] = e;
}

// ---------------- LSTM / concat (emit split bf16, [hi|hi|lo]) ----------------
__global__ void lstm_concat_b(const float* __restrict__ dyn, int t)
{
    int i = blockIdx.x * blockDim.x + threadIdx.x;
    if (i >= NN * KP1) return;
    int n = i / KP1, kk = i % KP1;
    int k = kk < 144 ? kk : kk < 288 ? kk - 144 : kk < 432 ? kk - 288 : -1;
    float v = 0.f;
    if (k >= 0 && k < KLSTM) v = (k < DD) ? dyn[(size_t)n * TT * DD + t * DD + k]
                                          : g_h[n * HL + (k - DD)];
    g_a2[(size_t)n * KP1 + kk] = (kk < 288) ? bf_hi(v) : bf_lo(v);
}

__device__ __forceinline__ float sigm(float x) { return 1.f / (1.f + expf(-x)); }

__global__ void lstm_point()
{
    int i = blockIdx.x * blockDim.x + threadIdx.x;
    if (i >= NN * HL) return;
    int n = i / HL, j = i % HL;
    const float* G = &g_feat[(size_t)n * HC];
    float ig = sigm(G[j]);
    float fg = sigm(G[HL + j]);
    float gg = tanhf(G[2 * HL + j]);
    float og = sigm(G[3 * HL + j]);
    float c = fg * g_c[i] + ig * gg;
    g_c[i] = c;
    g_h[i] = og * tanhf(c);
}

__global__ void gnn_concat_b(const float* __restrict__ xs)
{
    int i = blockIdx.x * blockDim.x + threadIdx.x;
    if (i >= NN * KP1) return;
    int n = i / KP1, kk = i % KP1;
    int k = kk < 144 ? kk : kk < 288 ? kk - 144 : kk < 432 ? kk - 288 : -1;
    float v = 0.f;
    if (k >= 0) v = (k < DS) ? xs[n * DS + k] : g_h[n * HL + (k - DS)];
    g_a2[(size_t)n * KP1 + kk] = (kk < 288) ? bf_hi(v) : bf_lo(v);
}

// ---------------- GAT: fused scores + online softmax (one warp per dst) ----------------
__global__ void gat_attn(const float* __restrict__ att)
{
    int d = (blockIdx.x * blockDim.x + threadIdx.x) >> 5;
    int lane = threadIdx.x & 31;
    if (d >= NN) return;
    int beg = g_rowoff[d], end = g_rowoff[d + 1];

    float xr[16], at[16];
    const float* xrp = g_xlr + (size_t)d * HC2 + HC;
#pragma unroll
    for (int q = 0; q < 16; q++) {
        xr[q] = xrp[q * 32 + lane];
        at[q] = __ldg(&att[q * 32 + lane]);
    }

    float m0 = -FLT_MAX, m1 = -FLT_MAX, m2 = -FLT_MAX, m3 = -FLT_MAX;
    float d0 = 0.f, d1 = 0.f, d2 = 0.f, d3 = 0.f;

    for (int j = beg; j < end; ++j) {
        int e = g_eid[j];
        const float* xlp = g_xlr + (size_t)g_src[e] * HC2;
        float p0 = 0.f, p1 = 0.f, p2 = 0.f, p3 = 0.f;
#pragma unroll
        for (int q = 0; q < 16; q++) {
            float v = xlp[q * 32 + lane] + xr[q];
            v = v > 0.f ? v : 0.2f * v;
            float pv = v * at[q];
            if (q < 4)       p0 += pv;
            else if (q < 8)  p1 += pv;
            else if (q < 12) p2 += pv;
            else             p3 += pv;
        }
#pragma unroll
        for (int o = 16; o; o >>= 1) {
            p0 += __shfl_xor_sync(0xffffffffu, p0, o);
            p1 += __shfl_xor_sync(0xffffffffu, p1, o);
            p2 += __shfl_xor_sync(0xffffffffu, p2, o);
            p3 += __shfl_xor_sync(0xffffffffu, p3, o);
        }
        float nm;
        nm = fmaxf(m0, p0); d0 = d0 * expf(m0 - nm) + expf(p0 - nm); m0 = nm;
        nm = fmaxf(m1, p1); d1 = d1 * expf(m1 - nm) + expf(p1 - nm); m1 = nm;
        nm = fmaxf(m2, p2); d2 = d2 * expf(m2 - nm) + expf(p2 - nm); m2 = nm;
        nm = fmaxf(m3, p3); d3 = d3 * expf(m3 - nm) + expf(p3 - nm); m3 = nm;
        if (lane == 0) {
            float* sp = &g_s[(size_t)e * GH];
            sp[0] = p0; sp[1] = p1; sp[2] = p2; sp[3] = p3;
        }
    }
    for (int j = beg + lane; j < end; j += 32) {
        int e = g_eid[j];
        float* sp = &g_s[(size_t)e * GH];
        sp[0] = expf(sp[0] - m0) / d0;
        sp[1] = expf(sp[1] - m1) / d1;
        sp[2] = expf(sp[2] - m2) / d2;
        sp[3] = expf(sp[3] - m3) / d3;
    }
}

__global__ void gat_agg()
{
    int d = blockIdx.x;
    int f = threadIdx.x;
    int h = f >> 7;
    int beg = g_rowoff[d], end = g_rowoff[d + 1];
    float acc = 0.f;
    for (int j = beg; j < end; ++j) {
        int e = g_eid[j];
        acc += g_s[(size_t)e * GH + h] * g_xlr[(size_t)g_src[e] * HC2 + f];
    }
    g_feat[(size_t)d * HC + f] = acc;
}

// ---------------- BatchNorm ----------------
__global__ void bn_reduce()
{
    int c = threadIdx.x;
    float s = 0.f, ss = 0.f;
    for (int r = blockIdx.x; r < NN; r += gridDim.x) {
        float v = g_feat[(size_t)r * HC + c];
        s += v; ss += v * v;
    }
    atomicAdd(&g_bnsum[c], s);
    atomicAdd(&g_bnsum[HC + c], ss);
}

__global__ void bn_final(const float* __restrict__ gamma, const float* __restrict__ beta)
{
    int c = threadIdx.x;
    float mean = g_bnsum[c] / (float)NN;
    float var  = g_bnsum[HC + c] / (float)NN - mean * mean;
    float k = gamma[c] * rsqrtf(var + 1e-5f);
    g_bnsc[c] = k;
    g_bnsc[HC + c] = beta[c] - mean * k;
}

// BN + ReLU, emit split bf16 into g_a2 [n, 1536] = [hi | hi | lo]
__global__ void bn_norm_relu_b()
{
    int i = blockIdx.x * blockDim.x + threadIdx.x;
    if (i >= NN * HC) return;
    int n = i >> 9, c = i & (HC - 1);
    float v = g_feat[i] * g_bnsc[c] + g_bnsc[HC + c];
    v = v > 0.f ? v : 0.f;
    __nv_bfloat16 hi = __float2bfloat16(v);
    __nv_bfloat16 lo = __float2bfloat16(v - __bfloat162float(hi));
    __nv_bfloat16* row = g_a2 + (size_t)n * KP2;
    row[c] = hi;
    row[512 + c] = hi;
    row[1024 + c] = lo;
}

// ---------------- host ----------------
static void* sym(const void* s) { void* p = nullptr; cudaGetSymbolAddress(&p, s); return p; }

extern "C" void kernel_launch(void* const* d_in, const int* in_sizes, int n_in,
                              void* d_out, int out_size)
{
    const float* x_static = (const float*)d_in[0];
    const float* dyn      = (const float*)d_in[1];
    const int*   ei       = (const int*)  d_in[2];
    const float* Wih      = (const float*)d_in[3];
    const float* Whh      = (const float*)d_in[4];
    const float* bih      = (const float*)d_in[5];
    const float* bhh      = (const float*)d_in[6];
    const float* Wl1      = (const float*)d_in[7];
    const float* Wr1      = (const float*)d_in[8];
    const float* att1     = (const float*)d_in[9];
    const float* Wl2      = (const float*)d_in[11];
    const float* Wr2      = (const float*)d_in[12];
    const float* att2     = (const float*)d_in[13];
    const float* gamma1   = (const float*)d_in[15];
    const float* beta1    = (const float*)d_in[16];
    const float* gamma2   = (const float*)d_in[17];
    const float* beta2    = (const float*)d_in[18];
    const float* Wp       = (const float*)d_in[19];
    const float* bp       = (const float*)d_in[20];
    float* out = (float*)d_out;

    __nv_bfloat16* pa2 = (__nv_bfloat16*)sym(g_a2);
    __nv_bfloat16* pwl = (__nv_bfloat16*)sym(g_wl);
    __nv_bfloat16* pw1 = (__nv_bfloat16*)sym(g_w1b);
    __nv_bfloat16* pw2 = (__nv_bfloat16*)sym(g_w2b);
    __nv_bfloat16* pwp = (__nv_bfloat16*)sym(g_wpb);
    float* pfeat = (float*)sym(g_feat);
    float* pxlr  = (float*)sym(g_xlr);
    float* pbcat = (float*)sym(g_bcat);
    float* ph    = (float*)sym(g_h);
    float* pc    = (float*)sym(g_c);
    float* psum  = (float*)sym(g_bnsum);
    int*   pcnt  = (int*)sym(g_counts);
    int*   prow  = (int*)sym(g_rowoff);
    int*   pcur  = (int*)sym(g_cursor);

    const int SM128 = (128 + 128) * 288;   // 73728 bytes (2 buffers, 72-elem stride)
    const int SM64  = (128 + 64) * 288;    // 55296
    cudaFuncSetAttribute((const void*)wgemm<128>, cudaFuncAttributeMaxDynamicSharedMemorySize, SM128);
    cudaFuncSetAttribute((const void*)wgemm<64>,  cudaFuncAttributeMaxDynamicSharedMemorySize, SM64);

    // ---- setup ----
    build_wlstm<<<(HC * KP1 + 255) / 256, 256>>>(Wih, Whh, bih, bhh);
    build_w1b<<<(HC2 * KP1 + 255) / 256, 256>>>(Wl1, Wr1);
    build_w2b<<<(HC2 * KP2 + 255) / 256, 256>>>(Wl2, Wr2);
    build_wpb<<<(EMB * KP2 + 255) / 256, 256>>>(Wp);
    cudaMemsetAsync(pcnt, 0, NN * sizeof(int));
    fill_edges<<<(ETOT + 255) / 256, 256>>>(ei);
    scan_rowoff<<<1, 1024>>>();
    cudaMemcpyAsync(pcur, prow, NN * sizeof(int), cudaMemcpyDeviceToDevice);
    scatter_edges<<<(ETOT + 255) / 256, 256>>>();
    cudaMemsetAsync(ph, 0, NN * HL * sizeof(float));
    cudaMemsetAsync(pc, 0, NN * HL * sizeof(float));

    const int MB = (NN + 127) / 128;   // 157

    for (int t = 0; t < TT; ++t) {
        // ---- LSTM ----
        lstm_concat_b<<<(NN * KP1 + 255) / 256, 256>>>(dyn, t);
        wgemm<128><<<dim3(HC / 128, MB), 256, SM128>>>(pa2, pwl, pfeat, pbcat,
                                                       NN, KP1, KP1, HC, KP1 / 64);
        lstm_point<<<(NN * HL + 255) / 256, 256>>>();

        // ---- GAT layer 1 ----
        gnn_concat_b<<<(NN * KP1 + 255) / 256, 256>>>(x_static);
        wgemm<128><<<dim3(HC2 / 128, MB), 256, SM128>>>(pa2, pw1, pxlr, nullptr,
                                                        NN, KP1, KP1, HC2, KP1 / 64);
        gat_attn<<<(NN * 32 + 127) / 128, 128>>>(att1);
        gat_agg<<<NN, HC>>>();
        cudaMemsetAsync(psum, 0, 2 * HC * sizeof(float));
        bn_reduce<<<256, HC>>>();
        bn_final<<<1, HC>>>(gamma1, beta1);
        bn_norm_relu_b<<<(NN * HC + 255) / 256, 256>>>();

        // ---- GAT layer 2 ----
        wgemm<128><<<dim3(HC2 / 128, MB), 256, SM128>>>(pa2, pw2, pxlr, nullptr,
                                                        NN, KP2, KP2, HC2, KP2 / 64);
        gat_attn<<<(NN * 32 + 127) / 128, 128>>>(att2);
        gat_agg<<<NN, HC>>>();
        cudaMemsetAsync(psum, 0, 2 * HC * sizeof(float));
        bn_reduce<<<256, HC>>>();
        bn_final<<<1, HC>>>(gamma2, beta2);
        bn_norm_relu_b<<<(NN * HC + 255) / 256, 256>>>();

        // ---- projection ----
        wgemm<64><<<dim3(EMB / 64, MB), 256, SM64>>>(pa2, pwp, out + t * EMB, bp,
                                                     NN, KP2, KP2, TT * EMB, KP2 / 64);
    }
    (void)in_sizes; (void)n_in; (void)out_size;
}

// round 17
// speedup vs baseline: 3.4890x; 1.3660x over previous
#include <cuda_runtime.h>
#include <cuda_bf16.h>
#include <math.h>
#include <float.h>
#include <stdint.h>

// ---------------- problem constants ----------------
#define NN      20000
#define TT      8
#define DS      16
#define DD      8
#define EE      320000
#define ETOT    (EE + NN)
#define HL      128
#define GH      4
#define GC      128
#define HC      512
#define HC2     1024
#define EMB     64
#define IN1     144        // DS + HL
#define KLSTM   136        // DD + HL

// split-K widths (activations [hi|hi|lo], weights [hi|lo|hi]; zero padded)
#define KP1     448        // 3*144 = 432 -> 448
#define KP2     1536       // 3*512

// ---------------- scratch (device globals) ----------------
__device__ __align__(16) float g_h[NN * HL];
__device__ __align__(16) float g_c[NN * HL];
__device__ __align__(16) float g_feat[NN * HC];
__device__ __align__(16) float g_xlr[(size_t)NN * HC2];
__device__ __align__(16) float g_bnsum[2 * HC];
__device__ __align__(16) float g_bnsc[2 * HC];
__device__ __align__(16) float g_bcat[HC];
__device__ __align__(16) __nv_bfloat16 g_a2[(size_t)NN * KP2];
__device__ __align__(16) __nv_bfloat16 g_wl[HC * KP1];
__device__ __align__(16) __nv_bfloat16 g_w1b[HC2 * KP1];
__device__ __align__(16) __nv_bfloat16 g_w2b[(size_t)HC2 * KP2];
__device__ __align__(16) __nv_bfloat16 g_wpb[EMB * KP2];
__device__ __align__(16) int g_counts[NN];
__device__ __align__(16) int g_rowoff[NN + 1];
__device__ __align__(16) int g_cursor[NN];
__device__ __align__(16) int g_eid[ETOT];
__device__ __align__(16) int g_src[ETOT];
__device__ __align__(16) int g_dst[ETOT];

// ---------------- helpers ----------------
__device__ __forceinline__ uint32_t smem_u32(const void* p) {
    uint32_t a;
    asm("{ .reg .u64 t; cvta.to.shared.u64 t, %1; cvt.u32.u64 %0, t; }" : "=r"(a) : "l"(p));
    return a;
}

__device__ __forceinline__ void mma16816(float* d, const uint32_t* a, const uint32_t* b)
{
    asm volatile(
        "mma.sync.aligned.m16n8k16.row.col.f32.bf16.bf16.f32 "
        "{%0,%1,%2,%3}, {%4,%5,%6,%7}, {%8,%9}, {%0,%1,%2,%3};"
        : "+f"(d[0]), "+f"(d[1]), "+f"(d[2]), "+f"(d[3])
        : "r"(a[0]), "r"(a[1]), "r"(a[2]), "r"(a[3]), "r"(b[0]), "r"(b[1]));
}

// =====================================================================
// Warp-MMA bf16 GEMM: C[m,n] = sum_k A[m,k]*B[n,k] (+bias[n]), fp32 acc.
// BM=128, BN=NT, BK=64. 256 threads = 8 warps (4 M x 2 N).
// =====================================================================
template <int NT>
__global__ __launch_bounds__(256, 2)
void wgemm(const __nv_bfloat16* __restrict__ A, const __nv_bfloat16* __restrict__ B,
           float* __restrict__ C, const float* __restrict__ bias,
           int M, int lda, int ldb, int ldc, int nch)
{
    constexpr int LDSE  = 72;                 // smem row stride (elems) = 144B
    constexpr int ASZ   = 128 * LDSE;
    constexpr int BSZ   = NT * LDSE;
    constexpr int STAGE = ASZ + BSZ;          // elems per buffer
    constexpr int NWT   = NT / 16;            // n-tiles (of 8) per warp

    extern __shared__ __nv_bfloat16 smw[];
    const uint32_t sbase = smem_u32(smw);

    const int tid  = threadIdx.x;
    const int lane = tid & 31, wid = tid >> 5;
    const int bm = blockIdx.y * 128;
    const int bn = blockIdx.x * NT;
    const int wm = (wid >> 1) * 32;
    const int wn = (wid & 1) * (NT / 2);

    float acc[2][NWT][4];
#pragma unroll
    for (int mt = 0; mt < 2; mt++)
#pragma unroll
        for (int nt = 0; nt < NWT; nt++)
#pragma unroll
            for (int q = 0; q < 4; q++) acc[mt][nt][q] = 0.f;

    const int lrow = tid >> 3;             // 0..31 (+32*i)
    const int lcol = (tid & 7) * 8;

    auto issue = [&](int c, int buf) {
        const int kof = c * 64;
        const uint32_t abase = sbase + (uint32_t)buf * STAGE * 2;
        const uint32_t bbase = abase + ASZ * 2;
#pragma unroll
        for (int i = 0; i < 4; i++) {
            int row = lrow + i * 32;
            uint32_t sa = abase + (uint32_t)(row * LDSE + lcol) * 2;
            int gr = bm + row;
            int sz = (gr < M) ? 16 : 0;
            if (gr >= M) gr = M - 1;
            const void* g = A + (size_t)gr * lda + kof + lcol;
            asm volatile("cp.async.cg.shared.global [%0], [%1], 16, %2;"
                         :: "r"(sa), "l"(g), "r"(sz));
        }
#pragma unroll
        for (int i = 0; i < NT / 32; i++) {
            int row = lrow + i * 32;
            uint32_t sa = bbase + (uint32_t)(row * LDSE + lcol) * 2;
            const void* g = B + (size_t)(bn + row) * ldb + kof + lcol;
            asm volatile("cp.async.cg.shared.global [%0], [%1], 16;"
                         :: "r"(sa), "l"(g));
        }
        asm volatile("cp.async.commit_group;" ::: "memory");
    };

    issue(0, 0);
    asm volatile("cp.async.wait_group 0;" ::: "memory");
    __syncthreads();

    for (int c = 0; c < nch; ++c) {
        const int buf = c & 1;
        const uint32_t abase = sbase + (uint32_t)buf * STAGE * 2;
        const uint32_t bbase = abase + ASZ * 2;

        if (c + 1 < nch) issue(c + 1, 1 - buf);

#pragma unroll
        for (int ks = 0; ks < 4; ++ks) {
            uint32_t afr[2][4];
#pragma unroll
            for (int mt = 0; mt < 2; mt++) {
                uint32_t ad = abase +
                    (uint32_t)((wm + mt * 16 + (lane & 15)) * LDSE + ks * 16 + (lane >> 4) * 8) * 2;
                asm volatile("ldmatrix.sync.aligned.m8n8.x4.shared.b16 {%0,%1,%2,%3}, [%4];"
                             : "=r"(afr[mt][0]), "=r"(afr[mt][1]),
                               "=r"(afr[mt][2]), "=r"(afr[mt][3]) : "r"(ad));
            }
            uint32_t bfr[NWT][2];
#pragma unroll
            for (int p = 0; p < NWT / 2; p++) {
                int grp = lane >> 3, r = lane & 7;
                int nrow = wn + p * 16 + (grp >> 1) * 8 + r;
                int kcol = ks * 16 + (grp & 1) * 8;
                uint32_t bd = bbase + (uint32_t)(nrow * LDSE + kcol) * 2;
                asm volatile("ldmatrix.sync.aligned.m8n8.x4.shared.b16 {%0,%1,%2,%3}, [%4];"
                             : "=r"(bfr[2 * p][0]), "=r"(bfr[2 * p][1]),
                               "=r"(bfr[2 * p + 1][0]), "=r"(bfr[2 * p + 1][1]) : "r"(bd));
            }
#pragma unroll
            for (int mt = 0; mt < 2; mt++)
#pragma unroll
                for (int nt = 0; nt < NWT; nt++)
                    mma16816(acc[mt][nt], afr[mt], bfr[nt]);
        }

        if (c + 1 < nch) {
            asm volatile("cp.async.wait_group 0;" ::: "memory");
            __syncthreads();
        }
    }

#pragma unroll
    for (int mt = 0; mt < 2; mt++) {
        int r0 = bm + wm + mt * 16 + (lane >> 2);
#pragma unroll
        for (int nt = 0; nt < NWT; nt++) {
            int n0 = bn + wn + nt * 8 + (lane & 3) * 2;
            float bx = 0.f, by = 0.f;
            if (bias) { bx = bias[n0]; by = bias[n0 + 1]; }
            if (r0 < M) {
                float2 v = make_float2(acc[mt][nt][0] + bx, acc[mt][nt][1] + by);
                *(float2*)(C + (size_t)r0 * ldc + n0) = v;
            }
            if (r0 + 8 < M) {
                float2 v = make_float2(acc[mt][nt][2] + bx, acc[mt][nt][3] + by);
                *(float2*)(C + (size_t)(r0 + 8) * ldc + n0) = v;
            }
        }
    }
}

// ---------------- bf16 split helpers ----------------
__device__ __forceinline__ __nv_bfloat16 bf_hi(float v) { return __float2bfloat16(v); }
__device__ __forceinline__ __nv_bfloat16 bf_lo(float v) {
    __nv_bfloat16 h = __float2bfloat16(v);
    return __float2bfloat16(v - __bfloat162float(h));
}

// ---------------- weight conversion: weights packed [hi | LO | hi] ----------------
__global__ void build_wlstm(const float* __restrict__ Wih, const float* __restrict__ Whh,
                            const float* __restrict__ bih, const float* __restrict__ bhh)
{
    int i = blockIdx.x * blockDim.x + threadIdx.x;
    if (i < HC) g_bcat[i] = bih[i] + bhh[i];
    if (i >= HC * KP1) return;
    int r = i / KP1, kk = i % KP1;
    int k = kk < 144 ? kk : kk < 288 ? kk - 144 : kk < 432 ? kk - 288 : -1;
    float v = 0.f;
    if (k >= 0 && k < KLSTM) v = (k < DD) ? Wih[r * DD + k] : Whh[r * HL + (k - DD)];
    g_wl[i] = (kk < 144) ? bf_hi(v) : (kk < 288) ? bf_lo(v) : bf_hi(v);
}

__global__ void build_w1b(const float* __restrict__ Wl, const float* __restrict__ Wr)
{
    int i = blockIdx.x * blockDim.x + threadIdx.x;
    if (i >= HC2 * KP1) return;
    int r = i / KP1, kk = i % KP1;
    int k = kk < 144 ? kk : kk < 288 ? kk - 144 : kk < 432 ? kk - 288 : -1;
    float v = 0.f;
    if (k >= 0) v = (r < HC) ? Wl[r * IN1 + k] : Wr[(r - HC) * IN1 + k];
    g_w1b[i] = (kk < 144) ? bf_hi(v) : (kk < 288) ? bf_lo(v) : bf_hi(v);
}

__global__ void build_w2b(const float* __restrict__ Wl, const float* __restrict__ Wr)
{
    size_t i = (size_t)blockIdx.x * blockDim.x + threadIdx.x;
    if (i >= (size_t)HC2 * KP2) return;
    int r = (int)(i / KP2), kk = (int)(i % KP2);
    int k = kk < 512 ? kk : kk < 1024 ? kk - 512 : kk - 1024;
    float v = (r < HC) ? Wl[r * HC + k] : Wr[(r - HC) * HC + k];
    g_w2b[i] = (kk < 512) ? bf_hi(v) : (kk < 1024) ? bf_lo(v) : bf_hi(v);
}

__global__ void build_wpb(const float* __restrict__ Wp)
{
    int i = blockIdx.x * blockDim.x + threadIdx.x;
    if (i >= EMB * KP2) return;
    int r = i / KP2, kk = i % KP2;
    int k = kk < 512 ? kk : kk < 1024 ? kk - 512 : kk - 1024;
    float v = Wp[r * HC + k];
    g_wpb[i] = (kk < 512) ? bf_hi(v) : (kk < 1024) ? bf_lo(v) : bf_hi(v);
}

// ---------------- CSR build ----------------
__global__ void fill_edges(const int* __restrict__ ei)
{
    int e = blockIdx.x * blockDim.x + threadIdx.x;
    if (e >= ETOT) return;
    int s, d;
    if (e < EE) { s = ei[e]; d = ei[EE + e]; }
    else        { s = d = e - EE; }
    g_src[e] = s; g_dst[e] = d;
    atomicAdd(&g_counts[d], 1);
}

__global__ void scan_rowoff()
{
    __shared__ int part[1024];
    int tid = threadIdx.x;
    const int chunk = (NN + 1023) / 1024;
    int start = tid * chunk;
    int lim = min(start + chunk, NN);
    int s = 0;
    for (int i = start; i < lim; i++) s += g_counts[i];
    part[tid] = s;
    __syncthreads();
    for (int off = 1; off < 1024; off <<= 1) {
        int v = (tid >= off) ? part[tid - off] : 0;
        __syncthreads();
        part[tid] += v;
        __syncthreads();
    }
    int run = (tid == 0) ? 0 : part[tid - 1];
    for (int i = start; i < lim; i++) { g_rowoff[i] = run; run += g_counts[i]; }
    if (tid == 1023) g_rowoff[NN] = part[1023];
}

__global__ void scatter_edges()
{
    int e = blockIdx.x * blockDim.x + threadIdx.x;
    if (e >= ETOT) return;
    int pos = atomicAdd(&g_cursor[g_dst[e]], 1);
    g_eid[pos] = e;
}

// ---------------- LSTM / concat (emit split bf16, [hi|hi|lo]) ----------------
__global__ void lstm_concat_b(const float* __restrict__ dyn, int t)
{
    int i = blockIdx.x * blockDim.x + threadIdx.x;
    if (i >= NN * KP1) return;
    int n = i / KP1, kk = i % KP1;
    int k = kk < 144 ? kk : kk < 288 ? kk - 144 : kk < 432 ? kk - 288 : -1;
    float v = 0.f;
    if (k >= 0 && k < KLSTM) v = (k < DD) ? dyn[(size_t)n * TT * DD + t * DD + k]
                                          : g_h[n * HL + (k - DD)];
    g_a2[(size_t)n * KP1 + kk] = (kk < 288) ? bf_hi(v) : bf_lo(v);
}

__device__ __forceinline__ float sigm(float x) { return 1.f / (1.f + expf(-x)); }

__global__ void lstm_point()
{
    int i = blockIdx.x * blockDim.x + threadIdx.x;
    if (i >= NN * HL) return;
    int n = i / HL, j = i % HL;
    const float* G = &g_feat[(size_t)n * HC];
    float ig = sigm(G[j]);
    float fg = sigm(G[HL + j]);
    float gg = tanhf(G[2 * HL + j]);
    float og = sigm(G[3 * HL + j]);
    float c = fg * g_c[i] + ig * gg;
    g_c[i] = c;
    g_h[i] = og * tanhf(c);
}

__global__ void gnn_concat_b(const float* __restrict__ xs)
{
    int i = blockIdx.x * blockDim.x + threadIdx.x;
    if (i >= NN * KP1) return;
    int n = i / KP1, kk = i % KP1;
    int k = kk < 144 ? kk : kk < 288 ? kk - 144 : kk < 432 ? kk - 288 : -1;
    float v = 0.f;
    if (k >= 0) v = (k < DS) ? xs[n * DS + k] : g_h[n * HL + (k - DS)];
    g_a2[(size_t)n * KP1 + kk] = (kk < 288) ? bf_hi(v) : bf_lo(v);
}

// =====================================================================
// GAT fused: scores + online softmax + aggregation, ONE pass over edges.
// One warp per dst. acc[16] per lane = full 512-ch output row.
// Writes acc/den straight into g_feat. xl row read once per edge.
// =====================================================================
__global__ __launch_bounds__(128)
void gat_fused(const float* __restrict__ att)
{
    int d = (blockIdx.x * blockDim.x + threadIdx.x) >> 5;
    int lane = threadIdx.x & 31;
    if (d >= NN) return;
    int beg = g_rowoff[d], end = g_rowoff[d + 1];

    float xr[16], at[16], acc[16];
    const float* xrp = g_xlr + (size_t)d * HC2 + HC;
#pragma unroll
    for (int q = 0; q < 16; q++) {
        xr[q] = xrp[q * 32 + lane];
        at[q] = __ldg(&att[q * 32 + lane]);
        acc[q] = 0.f;
    }

    float m0 = -FLT_MAX, m1 = -FLT_MAX, m2 = -FLT_MAX, m3 = -FLT_MAX;
    float d0 = 0.f, d1 = 0.f, d2 = 0.f, d3 = 0.f;

    for (int j = beg; j < end; ++j) {
        int e = g_eid[j];
        const float* xlp = g_xlr + (size_t)g_src[e] * HC2;
        float xl[16];
        float p0 = 0.f, p1 = 0.f, p2 = 0.f, p3 = 0.f;
#pragma unroll
        for (int q = 0; q < 16; q++) {
            xl[q] = xlp[q * 32 + lane];
            float v = xl[q] + xr[q];
            v = v > 0.f ? v : 0.2f * v;
            float pv = v * at[q];
            if (q < 4)       p0 += pv;
            else if (q < 8)  p1 += pv;
            else if (q < 12) p2 += pv;
            else             p3 += pv;
        }
#pragma unroll
        for (int o = 16; o; o >>= 1) {
            p0 += __shfl_xor_sync(0xffffffffu, p0, o);
            p1 += __shfl_xor_sync(0xffffffffu, p1, o);
            p2 += __shfl_xor_sync(0xffffffffu, p2, o);
            p3 += __shfl_xor_sync(0xffffffffu, p3, o);
        }
        // online softmax + rescaled accumulate (all lanes agree on p)
        float w0, w1, w2, w3;
        if (p0 > m0) {
            float sc = expf(m0 - p0); d0 *= sc;
#pragma unroll
            for (int q = 0; q < 4; q++) acc[q] *= sc;
            m0 = p0; w0 = 1.f;
        } else w0 = expf(p0 - m0);
        if (p1 > m1) {
            float sc = expf(m1 - p1); d1 *= sc;
#pragma unroll
            for (int q = 4; q < 8; q++) acc[q] *= sc;
            m1 = p1; w1 = 1.f;
        } else w1 = expf(p1 - m1);
        if (p2 > m2) {
            float sc = expf(m2 - p2); d2 *= sc;
#pragma unroll
            for (int q = 8; q < 12; q++) acc[q] *= sc;
            m2 = p2; w2 = 1.f;
        } else w2 = expf(p2 - m2);
        if (p3 > m3) {
            float sc = expf(m3 - p3); d3 *= sc;
#pragma unroll
            for (int q = 12; q < 16; q++) acc[q] *= sc;
            m3 = p3; w3 = 1.f;
        } else w3 = expf(p3 - m3);
        d0 += w0; d1 += w1; d2 += w2; d3 += w3;
#pragma unroll
        for (int q = 0; q < 16; q++) {
            float w = (q < 4) ? w0 : (q < 8) ? w1 : (q < 12) ? w2 : w3;
            acc[q] += w * xl[q];
        }
    }

    float* op = g_feat + (size_t)d * HC;
#pragma unroll
    for (int q = 0; q < 16; q++) {
        float den = (q < 4) ? d0 : (q < 8) ? d1 : (q < 12) ? d2 : d3;
        op[q * 32 + lane] = acc[q] / den;
    }
}

// ---------------- BatchNorm ----------------
__global__ void bn_reduce()
{
    int c = threadIdx.x;
    float s = 0.f, ss = 0.f;
    for (int r = blockIdx.x; r < NN; r += gridDim.x) {
        float v = g_feat[(size_t)r * HC + c];
        s += v; ss += v * v;
    }
    atomicAdd(&g_bnsum[c], s);
    atomicAdd(&g_bnsum[HC + c], ss);
}

__global__ void bn_final(const float* __restrict__ gamma, const float* __restrict__ beta)
{
    int c = threadIdx.x;
    float mean = g_bnsum[c] / (float)NN;
    float var  = g_bnsum[HC + c] / (float)NN - mean * mean;
    float k = gamma[c] * rsqrtf(var + 1e-5f);
    g_bnsc[c] = k;
    g_bnsc[HC + c] = beta[c] - mean * k;
}

// BN + ReLU, emit split bf16 into g_a2 [n, 1536] = [hi | hi | lo]
__global__ void bn_norm_relu_b()
{
    int i = blockIdx.x * blockDim.x + threadIdx.x;
    if (i >= NN * HC) return;
    int n = i >> 9, c = i & (HC - 1);
    float v = g_feat[i] * g_bnsc[c] + g_bnsc[HC + c];
    v = v > 0.f ? v : 0.f;
    __nv_bfloat16 hi = __float2bfloat16(v);
    __nv_bfloat16 lo = __float2bfloat16(v - __bfloat162float(hi));
    __nv_bfloat16* row = g_a2 + (size_t)n * KP2;
    row[c] = hi;
    row[512 + c] = hi;
    row[1024 + c] = lo;
}

// ---------------- host ----------------
static void* sym(const void* s) { void* p = nullptr; cudaGetSymbolAddress(&p, s); return p; }

extern "C" void kernel_launch(void* const* d_in, const int* in_sizes, int n_in,
                              void* d_out, int out_size)
{
    const float* x_static = (const float*)d_in[0];
    const float* dyn      = (const float*)d_in[1];
    const int*   ei       = (const int*)  d_in[2];
    const float* Wih      = (const float*)d_in[3];
    const float* Whh      = (const float*)d_in[4];
    const float* bih      = (const float*)d_in[5];
    const float* bhh      = (const float*)d_in[6];
    const float* Wl1      = (const float*)d_in[7];
    const float* Wr1      = (const float*)d_in[8];
    const float* att1     = (const float*)d_in[9];
    const float* Wl2      = (const float*)d_in[11];
    const float* Wr2      = (const float*)d_in[12];
    const float* att2     = (const float*)d_in[13];
    const float* gamma1   = (const float*)d_in[15];
    const float* beta1    = (const float*)d_in[16];
    const float* gamma2   = (const float*)d_in[17];
    const float* beta2    = (const float*)d_in[18];
    const float* Wp       = (const float*)d_in[19];
    const float* bp       = (const float*)d_in[20];
    float* out = (float*)d_out;

    __nv_bfloat16* pa2 = (__nv_bfloat16*)sym(g_a2);
    __nv_bfloat16* pwl = (__nv_bfloat16*)sym(g_wl);
    __nv_bfloat16* pw1 = (__nv_bfloat16*)sym(g_w1b);
    __nv_bfloat16* pw2 = (__nv_bfloat16*)sym(g_w2b);
    __nv_bfloat16* pwp = (__nv_bfloat16*)sym(g_wpb);
    float* pfeat = (float*)sym(g_feat);
    float* pxlr  = (float*)sym(g_xlr);
    float* pbcat = (float*)sym(g_bcat);
    float* ph    = (float*)sym(g_h);
    float* pc    = (float*)sym(g_c);
    float* psum  = (float*)sym(g_bnsum);
    int*   pcnt  = (int*)sym(g_counts);
    int*   prow  = (int*)sym(g_rowoff);
    int*   pcur  = (int*)sym(g_cursor);

    const int SM128 = (128 + 128) * 288;   // 73728 bytes
    const int SM64  = (128 + 64) * 288;    // 55296
    cudaFuncSetAttribute((const void*)wgemm<128>, cudaFuncAttributeMaxDynamicSharedMemorySize, SM128);
    cudaFuncSetAttribute((const void*)wgemm<64>,  cudaFuncAttributeMaxDynamicSharedMemorySize, SM64);

    // ---- setup ----
    build_wlstm<<<(HC * KP1 + 255) / 256, 256>>>(Wih, Whh, bih, bhh);
    build_w1b<<<(HC2 * KP1 + 255) / 256, 256>>>(Wl1, Wr1);
    build_w2b<<<(HC2 * KP2 + 255) / 256, 256>>>(Wl2, Wr2);
    build_wpb<<<(EMB * KP2 + 255) / 256, 256>>>(Wp);
    cudaMemsetAsync(pcnt, 0, NN * sizeof(int));
    fill_edges<<<(ETOT + 255) / 256, 256>>>(ei);
    scan_rowoff<<<1, 1024>>>();
    cudaMemcpyAsync(pcur, prow, NN * sizeof(int), cudaMemcpyDeviceToDevice);
    scatter_edges<<<(ETOT + 255) / 256, 256>>>();
    cudaMemsetAsync(ph, 0, NN * HL * sizeof(float));
    cudaMemsetAsync(pc, 0, NN * HL * sizeof(float));

    const int MB = (NN + 127) / 128;   // 157

    for (int t = 0; t < TT; ++t) {
        // ---- LSTM ----
        lstm_concat_b<<<(NN * KP1 + 255) / 256, 256>>>(dyn, t);
        wgemm<128><<<dim3(HC / 128, MB), 256, SM128>>>(pa2, pwl, pfeat, pbcat,
                                                       NN, KP1, KP1, HC, KP1 / 64);
        lstm_point<<<(NN * HL + 255) / 256, 256>>>();

        // ---- GAT layer 1 ----
        gnn_concat_b<<<(NN * KP1 + 255) / 256, 256>>>(x_static);
        wgemm<128><<<dim3(HC2 / 128, MB), 256, SM128>>>(pa2, pw1, pxlr, nullptr,
                                                        NN, KP1, KP1, HC2, KP1 / 64);
        gat_fused<<<(NN * 32 + 127) / 128, 128>>>(att1);
        cudaMemsetAsync(psum, 0, 2 * HC * sizeof(float));
        bn_reduce<<<256, HC>>>();
        bn_final<<<1, HC>>>(gamma1, beta1);
        bn_norm_relu_b<<<(NN * HC + 255) / 256, 256>>>();

        // ---- GAT layer 2 ----
        wgemm<128><<<dim3(HC2 / 128, MB), 256, SM128>>>(pa2, pw2, pxlr, nullptr,
                                                        NN, KP2, KP2, HC2, KP2 / 64);
        gat_fused<<<(NN * 32 + 127) / 128, 128>>>(att2);
        cudaMemsetAsync(psum, 0, 2 * HC * sizeof(float));
        bn_reduce<<<256, HC>>>();
        bn_final<<<1, HC>>>(gamma2, beta2);
        bn_norm_relu_b<<<(NN * HC + 255) / 256, 256>>>();

        // ---- projection ----
        wgemm<64><<<dim3(EMB / 64, MB), 256, SM64>>>(pa2, pwp, out + t * EMB, bp,
                                                     NN, KP2, KP2, TT * EMB, KP2 / 64);
    }
    (void)in_sizes; (void)n_in; (void)out_size;
}